// round 2
// baseline (speedup 1.0000x reference)
#include <cuda_runtime.h>
#include <math.h>

#define NN 50000
#define SLOPE 0.2f

// ---- scratch (alloc-free: __device__ globals) ----
__device__ float g_sumcap[NN];
__device__ float g_s1[2 * NN];
__device__ float g_S1[2 * NN];
__device__ float g_S2[2 * NN];
__device__ float g_ft2[2 * NN];
__device__ float g_s2[2 * NN];
__device__ float g_acc2[2 * NN];
__device__ float g_xfin[NN];
__device__ float g_c1[6];   // cl1[2], cr1[2], ce1[2]

// Precompute collapsed layer-1 attention coefficients:
// cl1[h] = sum_d W1[h,d]*al1[h,d], cr1[h] = sum_d W1[h,d]*ar1[h,d],
// ce1[h] = sum_d We1[h,d]*ae1[h,d]
__global__ void k_prep(const float* __restrict__ W1, const float* __restrict__ We1,
                       const float* __restrict__ al1, const float* __restrict__ ar1,
                       const float* __restrict__ ae1) {
    int h = threadIdx.x;
    if (h < 2) {
        float cl = 0.f, cr = 0.f, ce = 0.f;
        #pragma unroll
        for (int d = 0; d < 16; ++d) {
            float w = W1[h * 16 + d];
            cl += w * al1[h * 16 + d];
            cr += w * ar1[h * 16 + d];
            ce += We1[h * 16 + d] * ae1[h * 16 + d];
        }
        g_c1[h] = cl; g_c1[2 + h] = cr; g_c1[4 + h] = ce;
    }
}

__global__ void k_init() {
    int i = blockIdx.x * blockDim.x + threadIdx.x;
    if (i < NN) g_sumcap[i] = 0.f;
    if (i < 2 * NN) {
        g_s1[i] = 0.f; g_S1[i] = 0.f; g_S2[i] = 0.f;
        g_s2[i] = 0.f; g_acc2[i] = 0.f;
    }
}

// sum of incoming edge capacities per node
__global__ void k_sumcap(const int* __restrict__ dst, const float* __restrict__ cap, int E) {
    int e = blockIdx.x * blockDim.x + threadIdx.x;
    if (e < E) atomicAdd(&g_sumcap[dst[e]], cap[e]);
}

// layer-1 softmax denominator (no max-shift: logits are small & bounded)
__global__ void k_l1_den(const int* __restrict__ src, const int* __restrict__ dst,
                         const float* __restrict__ ef, int E) {
    int e = blockIdx.x * blockDim.x + threadIdx.x;
    if (e >= E) return;
    int s = src[e], d = dst[e];
    float ss = g_sumcap[s], sd = g_sumcap[d], f = ef[e];
    #pragma unroll
    for (int h = 0; h < 2; ++h) {
        float v = g_c1[h] * ss + g_c1[2 + h] * sd + g_c1[4 + h] * f;
        v = v > 0.f ? v : SLOPE * v;
        atomicAdd(&g_s1[2 * d + h], __expf(v));
    }
}

// layer-1 weighted accumulation of the two scalar factors
__global__ void k_l1_acc(const int* __restrict__ src, const int* __restrict__ dst,
                         const float* __restrict__ ef, int E) {
    int e = blockIdx.x * blockDim.x + threadIdx.x;
    if (e >= E) return;
    int s = src[e], d = dst[e];
    float ss = g_sumcap[s], sd = g_sumcap[d], f = ef[e];
    #pragma unroll
    for (int h = 0; h < 2; ++h) {
        float v = g_c1[h] * ss + g_c1[2 + h] * sd + g_c1[4 + h] * f;
        v = v > 0.f ? v : SLOPE * v;
        float a = __expf(v) / g_s1[2 * d + h];
        atomicAdd(&g_S1[2 * d + h], a * ss);
        atomicAdd(&g_S2[2 * d + h], a * f);
    }
}

// node: reconstruct x[n,16] = relu(sum_h W1[h,:]*S1 + We1[h,:]*S2 + b1[h,:]),
// then project to layer-2 features ft2[n,h2] = x . W2[:,h2]
__global__ void k_node1(const float* __restrict__ W1, const float* __restrict__ We1,
                        const float* __restrict__ b1, const float* __restrict__ W2) {
    int n = blockIdx.x * blockDim.x + threadIdx.x;
    if (n >= NN) return;
    float s10 = g_S1[2 * n], s11 = g_S1[2 * n + 1];
    float s20 = g_S2[2 * n], s21 = g_S2[2 * n + 1];
    float ft0 = 0.f, ft1 = 0.f;
    #pragma unroll
    for (int d = 0; d < 16; ++d) {
        float x = W1[d] * s10 + We1[d] * s20 + b1[d]
                + W1[16 + d] * s11 + We1[16 + d] * s21 + b1[16 + d];
        x = fmaxf(x, 0.f);
        ft0 += x * W2[2 * d];
        ft1 += x * W2[2 * d + 1];
    }
    g_ft2[2 * n] = ft0;
    g_ft2[2 * n + 1] = ft1;
}

// layer-2 softmax denominator
__global__ void k_l2_den(const int* __restrict__ src, const int* __restrict__ dst,
                         const float* __restrict__ ef,
                         const float* __restrict__ We2, const float* __restrict__ al2,
                         const float* __restrict__ ar2, const float* __restrict__ ae2, int E) {
    int e = blockIdx.x * blockDim.x + threadIdx.x;
    if (e >= E) return;
    int s = src[e], d = dst[e];
    float f = ef[e];
    #pragma unroll
    for (int h = 0; h < 2; ++h) {
        float v = al2[h] * g_ft2[2 * s + h] + ar2[h] * g_ft2[2 * d + h]
                + ae2[h] * We2[h] * f;
        v = v > 0.f ? v : SLOPE * v;
        atomicAdd(&g_s2[2 * d + h], __expf(v));
    }
}

// layer-2 weighted message accumulation
__global__ void k_l2_acc(const int* __restrict__ src, const int* __restrict__ dst,
                         const float* __restrict__ ef,
                         const float* __restrict__ We2, const float* __restrict__ al2,
                         const float* __restrict__ ar2, const float* __restrict__ ae2, int E) {
    int e = blockIdx.x * blockDim.x + threadIdx.x;
    if (e >= E) return;
    int s = src[e], d = dst[e];
    float f = ef[e];
    #pragma unroll
    for (int h = 0; h < 2; ++h) {
        float fts = g_ft2[2 * s + h];
        float v = al2[h] * fts + ar2[h] * g_ft2[2 * d + h] + ae2[h] * We2[h] * f;
        v = v > 0.f ? v : SLOPE * v;
        float a = __expf(v) / g_s2[2 * d + h];
        atomicAdd(&g_acc2[2 * d + h], a * (fts + We2[h] * f));
    }
}

__global__ void k_node2(const float* __restrict__ b2) {
    int n = blockIdx.x * blockDim.x + threadIdx.x;
    if (n >= NN) return;
    g_xfin[n] = g_acc2[2 * n] + g_acc2[2 * n + 1] + b2[0] + b2[1];
}

__global__ void k_out(const int* __restrict__ src, const int* __restrict__ dst,
                      float* __restrict__ out, int E) {
    int e = blockIdx.x * blockDim.x + threadIdx.x;
    if (e >= E) return;
    out[e] = sqrtf(g_xfin[src[e]] * g_xfin[dst[e]]);
}

extern "C" void kernel_launch(void* const* d_in, const int* in_sizes, int n_in,
                              void* d_out, int out_size) {
    const int*   src = (const int*)d_in[0];
    const int*   dst = (const int*)d_in[1];
    const float* cap = (const float*)d_in[2];
    const float* ef  = (const float*)d_in[3];
    const float* W1  = (const float*)d_in[4];
    const float* We1 = (const float*)d_in[5];
    const float* al1 = (const float*)d_in[6];
    const float* ar1 = (const float*)d_in[7];
    const float* ae1 = (const float*)d_in[8];
    const float* b1  = (const float*)d_in[9];
    const float* W2  = (const float*)d_in[10];
    const float* We2 = (const float*)d_in[11];
    const float* al2 = (const float*)d_in[12];
    const float* ar2 = (const float*)d_in[13];
    const float* ae2 = (const float*)d_in[14];
    const float* b2  = (const float*)d_in[15];
    float* out = (float*)d_out;

    const int E = in_sizes[0];
    const int TB = 256;
    const int eb  = (E + TB - 1) / TB;
    const int nb  = (NN + TB - 1) / TB;
    const int nb2 = (2 * NN + TB - 1) / TB;

    k_prep<<<1, 32>>>(W1, We1, al1, ar1, ae1);
    k_init<<<nb2, TB>>>();
    k_sumcap<<<eb, TB>>>(dst, cap, E);
    k_l1_den<<<eb, TB>>>(src, dst, ef, E);
    k_l1_acc<<<eb, TB>>>(src, dst, ef, E);
    k_node1<<<nb, TB>>>(W1, We1, b1, W2);
    k_l2_den<<<eb, TB>>>(src, dst, ef, We2, al2, ar2, ae2, E);
    k_l2_acc<<<eb, TB>>>(src, dst, ef, We2, al2, ar2, ae2, E);
    k_node2<<<nb, TB>>>(b2);
    k_out<<<eb, TB>>>(src, dst, out, E);
}

// round 3
// speedup vs baseline: 2.3514x; 2.3514x over previous
#include <cuda_runtime.h>
#include <math.h>

#define NN 50000
#define SLOPE 0.2f

// ---- scratch (alloc-free: __device__ globals) ----
__device__ float  g_sumcap[NN];
__device__ __align__(16) float g_A1[8 * NN];  // per node: {e0, e0*ss, e0*f, e1, e1*ss, e1*f, pad, pad}
__device__ __align__(16) float g_A2[4 * NN];  // per node: {e0, m0, e1, m1}
__device__ float2 g_ft2[NN];
__device__ float  g_xfin[NN];
__device__ float  g_c1[6];   // cl1[2], cr1[2], ce1[2]

// Collapsed layer-1 attention coefficients (1-d input feature makes the
// 16-wide dots factor into 3 scalars per head).
__global__ void k_prep(const float* __restrict__ W1, const float* __restrict__ We1,
                       const float* __restrict__ al1, const float* __restrict__ ar1,
                       const float* __restrict__ ae1) {
    int h = threadIdx.x;
    if (h < 2) {
        float cl = 0.f, cr = 0.f, ce = 0.f;
        #pragma unroll
        for (int d = 0; d < 16; ++d) {
            float w = W1[h * 16 + d];
            cl += w * al1[h * 16 + d];
            cr += w * ar1[h * 16 + d];
            ce += We1[h * 16 + d] * ae1[h * 16 + d];
        }
        g_c1[h] = cl; g_c1[2 + h] = cr; g_c1[4 + h] = ce;
    }
}

__global__ void k_init() {
    int i = blockIdx.x * blockDim.x + threadIdx.x;
    if (i < NN) g_sumcap[i] = 0.f;
    if (i < 8 * NN) g_A1[i] = 0.f;
    if (i < 4 * NN) g_A2[i] = 0.f;
}

// pass 1: per-node sum of incoming capacities
__global__ void k_sumcap(const int* __restrict__ dst, const float* __restrict__ cap, int E) {
    int e = blockIdx.x * blockDim.x + threadIdx.x;
    if (e < E) atomicAdd(&g_sumcap[dst[e]], cap[e]);
}

// pass 2: layer-1 fused softmax-numerator/denominator accumulation.
// a = exp(v)/sum(exp) => accumulate {exp, exp*ss, exp*f}; divide in k_node1.
// (no max-shift: logits are small & bounded, exp cannot overflow)
__global__ void k_l1(const int* __restrict__ src, const int* __restrict__ dst,
                     const float* __restrict__ ef, int E) {
    int e = blockIdx.x * blockDim.x + threadIdx.x;
    if (e >= E) return;
    int s = src[e], d = dst[e];
    float ss = g_sumcap[s], sd = g_sumcap[d], f = ef[e];

    float v0 = g_c1[0] * ss + g_c1[2] * sd + g_c1[4] * f;
    v0 = v0 > 0.f ? v0 : SLOPE * v0;
    float e0 = __expf(v0);
    float v1 = g_c1[1] * ss + g_c1[3] * sd + g_c1[5] * f;
    v1 = v1 > 0.f ? v1 : SLOPE * v1;
    float e1 = __expf(v1);

    float4* p4 = (float4*)&g_A1[8 * d];
    atomicAdd(p4, make_float4(e0, e0 * ss, e0 * f, e1));
    float2* p2 = (float2*)&g_A1[8 * d + 4];
    atomicAdd(p2, make_float2(e1 * ss, e1 * f));
}

// node: normalize, reconstruct x[n,16] = relu(.), project to layer-2 feats
__global__ void k_node1(const float* __restrict__ W1, const float* __restrict__ We1,
                        const float* __restrict__ b1, const float* __restrict__ W2) {
    int n = blockIdx.x * blockDim.x + threadIdx.x;
    if (n >= NN) return;
    float4 a = *(const float4*)&g_A1[8 * n];
    float2 b = *(const float2*)&g_A1[8 * n + 4];
    float inv0 = 1.f / a.x, inv1 = 1.f / a.w;   // self-loop guarantees > 0
    float s10 = a.y * inv0, s20 = a.z * inv0;
    float s11 = b.x * inv1, s21 = b.y * inv1;
    float ft0 = 0.f, ft1 = 0.f;
    #pragma unroll
    for (int d = 0; d < 16; ++d) {
        float x = W1[d] * s10 + We1[d] * s20 + b1[d]
                + W1[16 + d] * s11 + We1[16 + d] * s21 + b1[16 + d];
        x = fmaxf(x, 0.f);
        ft0 += x * W2[2 * d];
        ft1 += x * W2[2 * d + 1];
    }
    g_ft2[n] = make_float2(ft0, ft1);
}

// pass 3: layer-2 fused attention accumulation: {exp, exp*msg} per head,
// one float4 red op per edge.
__global__ void k_l2(const int* __restrict__ src, const int* __restrict__ dst,
                     const float* __restrict__ ef,
                     const float* __restrict__ We2, const float* __restrict__ al2,
                     const float* __restrict__ ar2, const float* __restrict__ ae2, int E) {
    int e = blockIdx.x * blockDim.x + threadIdx.x;
    if (e >= E) return;
    int s = src[e], d = dst[e];
    float f = ef[e];
    float2 fts = g_ft2[s];
    float2 ftd = g_ft2[d];

    float w0 = We2[0] * f, w1 = We2[1] * f;
    float v0 = al2[0] * fts.x + ar2[0] * ftd.x + ae2[0] * w0;
    v0 = v0 > 0.f ? v0 : SLOPE * v0;
    float e0 = __expf(v0);
    float v1 = al2[1] * fts.y + ar2[1] * ftd.y + ae2[1] * w1;
    v1 = v1 > 0.f ? v1 : SLOPE * v1;
    float e1 = __expf(v1);

    float4* p4 = (float4*)&g_A2[4 * d];
    atomicAdd(p4, make_float4(e0, e0 * (fts.x + w0), e1, e1 * (fts.y + w1)));
}

__global__ void k_node2(const float* __restrict__ b2) {
    int n = blockIdx.x * blockDim.x + threadIdx.x;
    if (n >= NN) return;
    float4 a = *(const float4*)&g_A2[4 * n];
    g_xfin[n] = a.y / a.x + a.w / a.z + b2[0] + b2[1];
}

// pass 4: edge output
__global__ void k_out(const int* __restrict__ src, const int* __restrict__ dst,
                      float* __restrict__ out, int E) {
    int e = blockIdx.x * blockDim.x + threadIdx.x;
    if (e >= E) return;
    out[e] = sqrtf(g_xfin[src[e]] * g_xfin[dst[e]]);
}

extern "C" void kernel_launch(void* const* d_in, const int* in_sizes, int n_in,
                              void* d_out, int out_size) {
    const int*   src = (const int*)d_in[0];
    const int*   dst = (const int*)d_in[1];
    const float* cap = (const float*)d_in[2];
    const float* ef  = (const float*)d_in[3];
    const float* W1  = (const float*)d_in[4];
    const float* We1 = (const float*)d_in[5];
    const float* al1 = (const float*)d_in[6];
    const float* ar1 = (const float*)d_in[7];
    const float* ae1 = (const float*)d_in[8];
    const float* b1  = (const float*)d_in[9];
    const float* W2  = (const float*)d_in[10];
    const float* We2 = (const float*)d_in[11];
    const float* al2 = (const float*)d_in[12];
    const float* ar2 = (const float*)d_in[13];
    const float* ae2 = (const float*)d_in[14];
    const float* b2  = (const float*)d_in[15];
    float* out = (float*)d_out;

    const int E = in_sizes[0];
    const int TB = 256;
    const int eb  = (E + TB - 1) / TB;
    const int nb  = (NN + TB - 1) / TB;
    const int nb8 = (8 * NN + TB - 1) / TB;

    k_prep<<<1, 32>>>(W1, We1, al1, ar1, ae1);
    k_init<<<nb8, TB>>>();
    k_sumcap<<<eb, TB>>>(dst, cap, E);
    k_l1<<<eb, TB>>>(src, dst, ef, E);
    k_node1<<<nb, TB>>>(W1, We1, b1, W2);
    k_l2<<<eb, TB>>>(src, dst, ef, We2, al2, ar2, ae2, E);
    k_node2<<<nb, TB>>>(b2);
    k_out<<<eb, TB>>>(src, dst, out, E);
}

// round 5
// speedup vs baseline: 2.3724x; 1.0089x over previous
#include <cuda_runtime.h>
#include <math.h>

#define NN 50000
#define SLOPE 0.2f

// ---- scratch (alloc-free: __device__ globals) ----
__device__ float  g_sumcap[NN];
__device__ __align__(16) float g_A1[8 * NN];  // per node: {e0, e0*ss, e0*f, e1, e1*ss, e1*f, pad, pad}
__device__ __align__(16) float g_A2[4 * NN];  // per node: {e0, m0, e1, m1}
__device__ float2 g_ft2[NN];
__device__ float  g_xfin[NN];
__device__ float  g_c1[6];   // cl1[2], cr1[2], ce1[2]

// init scratch + (block 0) compute collapsed layer-1 attention coefficients
__global__ void k_init(const float* __restrict__ W1, const float* __restrict__ We1,
                       const float* __restrict__ al1, const float* __restrict__ ar1,
                       const float* __restrict__ ae1) {
    int i = blockIdx.x * blockDim.x + threadIdx.x;
    if (i < NN) g_sumcap[i] = 0.f;
    if (i < 8 * NN) g_A1[i] = 0.f;
    if (i < 4 * NN) g_A2[i] = 0.f;
    if (i < 2) {
        int h = i;
        float cl = 0.f, cr = 0.f, ce = 0.f;
        #pragma unroll
        for (int d = 0; d < 16; ++d) {
            float w = W1[h * 16 + d];
            cl += w * al1[h * 16 + d];
            cr += w * ar1[h * 16 + d];
            ce += We1[h * 16 + d] * ae1[h * 16 + d];
        }
        g_c1[h] = cl; g_c1[2 + h] = cr; g_c1[4 + h] = ce;
    }
}

// pass 1: per-node sum of incoming capacities (4 edges/thread)
__global__ void k_sumcap(const int* __restrict__ dst, const float* __restrict__ cap, int E) {
    int t = blockIdx.x * blockDim.x + threadIdx.x;
    int e = 4 * t;
    if (e + 3 < E) {
        int4   d = *(const int4*)(dst + e);
        float4 c = *(const float4*)(cap + e);
        atomicAdd(&g_sumcap[d.x], c.x);
        atomicAdd(&g_sumcap[d.y], c.y);
        atomicAdd(&g_sumcap[d.z], c.z);
        atomicAdd(&g_sumcap[d.w], c.w);
    } else {
        for (; e < E; ++e) atomicAdd(&g_sumcap[dst[e]], cap[e]);
    }
}

// pass 2: layer-1 fused softmax num/den accumulation (4 edges/thread).
// a = exp(v)/sum(exp) => accumulate {exp, exp*ss, exp*f}; divide in k_node1.
__device__ __forceinline__ void l1_edge(int s, int d, float f,
                                        float c0, float c1, float c2,
                                        float c3, float c4, float c5, float ss) {
    float sd = g_sumcap[d];
    float v0 = c0 * ss + c2 * sd + c4 * f;
    v0 = v0 > 0.f ? v0 : SLOPE * v0;
    float e0 = __expf(v0);
    float v1 = c1 * ss + c3 * sd + c5 * f;
    v1 = v1 > 0.f ? v1 : SLOPE * v1;
    float e1 = __expf(v1);
    atomicAdd((float4*)&g_A1[8 * d], make_float4(e0, e0 * ss, e0 * f, e1));
    atomicAdd((float2*)&g_A1[8 * d + 4], make_float2(e1 * ss, e1 * f));
}

__global__ void k_l1(const int* __restrict__ src, const int* __restrict__ dst,
                     const float* __restrict__ ef, int E) {
    int t = blockIdx.x * blockDim.x + threadIdx.x;
    int e = 4 * t;
    float c0 = g_c1[0], c1 = g_c1[1], c2 = g_c1[2],
          c3 = g_c1[3], c4 = g_c1[4], c5 = g_c1[5];
    if (e + 3 < E) {
        int4   s = *(const int4*)(src + e);
        int4   d = *(const int4*)(dst + e);
        float4 f = *(const float4*)(ef + e);
        // batch all gathers up front for MLP
        float ssx = g_sumcap[s.x], ssy = g_sumcap[s.y],
              ssz = g_sumcap[s.z], ssw = g_sumcap[s.w];
        l1_edge(s.x, d.x, f.x, c0, c1, c2, c3, c4, c5, ssx);
        l1_edge(s.y, d.y, f.y, c0, c1, c2, c3, c4, c5, ssy);
        l1_edge(s.z, d.z, f.z, c0, c1, c2, c3, c4, c5, ssz);
        l1_edge(s.w, d.w, f.w, c0, c1, c2, c3, c4, c5, ssw);
    } else {
        for (; e < E; ++e)
            l1_edge(src[e], dst[e], ef[e], c0, c1, c2, c3, c4, c5, g_sumcap[src[e]]);
    }
}

// node: normalize, reconstruct x[n,16] = relu(.), project to layer-2 feats
__global__ void k_node1(const float* __restrict__ W1, const float* __restrict__ We1,
                        const float* __restrict__ b1, const float* __restrict__ W2) {
    int n = blockIdx.x * blockDim.x + threadIdx.x;
    if (n >= NN) return;
    float4 a = *(const float4*)&g_A1[8 * n];
    float2 b = *(const float2*)&g_A1[8 * n + 4];
    float inv0 = 1.f / a.x, inv1 = 1.f / a.w;   // self-loop guarantees > 0
    float s10 = a.y * inv0, s20 = a.z * inv0;
    float s11 = b.x * inv1, s21 = b.y * inv1;
    float ft0 = 0.f, ft1 = 0.f;
    #pragma unroll
    for (int d = 0; d < 16; ++d) {
        float x = W1[d] * s10 + We1[d] * s20 + b1[d]
                + W1[16 + d] * s11 + We1[16 + d] * s21 + b1[16 + d];
        x = fmaxf(x, 0.f);
        ft0 += x * W2[2 * d];
        ft1 += x * W2[2 * d + 1];
    }
    g_ft2[n] = make_float2(ft0, ft1);
}

// pass 3: layer-2 fused attention accumulation (4 edges/thread)
__device__ __forceinline__ void l2_edge(float2 fts, float2 ftd, int d, float f,
                                        float al0, float al1, float ar0, float ar1,
                                        float ae0, float ae1, float we0, float we1) {
    float w0 = we0 * f, w1 = we1 * f;
    float v0 = al0 * fts.x + ar0 * ftd.x + ae0 * w0;
    v0 = v0 > 0.f ? v0 : SLOPE * v0;
    float e0 = __expf(v0);
    float v1 = al1 * fts.y + ar1 * ftd.y + ae1 * w1;
    v1 = v1 > 0.f ? v1 : SLOPE * v1;
    float e1 = __expf(v1);
    atomicAdd((float4*)&g_A2[4 * d],
              make_float4(e0, e0 * (fts.x + w0), e1, e1 * (fts.y + w1)));
}

__global__ void k_l2(const int* __restrict__ src, const int* __restrict__ dst,
                     const float* __restrict__ ef,
                     const float* __restrict__ We2, const float* __restrict__ al2,
                     const float* __restrict__ ar2, const float* __restrict__ ae2, int E) {
    int t = blockIdx.x * blockDim.x + threadIdx.x;
    int e = 4 * t;
    float al0 = al2[0], al1 = al2[1], ar0 = ar2[0], ar1 = ar2[1];
    float ae0 = ae2[0], ae1 = ae2[1], we0 = We2[0], we1 = We2[1];
    if (e + 3 < E) {
        int4   s = *(const int4*)(src + e);
        int4   d = *(const int4*)(dst + e);
        float4 f = *(const float4*)(ef + e);
        // batch all 8 gathers for MLP
        float2 fsx = g_ft2[s.x], fsy = g_ft2[s.y], fsz = g_ft2[s.z], fsw = g_ft2[s.w];
        float2 fdx = g_ft2[d.x], fdy = g_ft2[d.y], fdz = g_ft2[d.z], fdw = g_ft2[d.w];
        l2_edge(fsx, fdx, d.x, f.x, al0, al1, ar0, ar1, ae0, ae1, we0, we1);
        l2_edge(fsy, fdy, d.y, f.y, al0, al1, ar0, ar1, ae0, ae1, we0, we1);
        l2_edge(fsz, fdz, d.z, f.z, al0, al1, ar0, ar1, ae0, ae1, we0, we1);
        l2_edge(fsw, fdw, d.w, f.w, al0, al1, ar0, ar1, ae0, ae1, we0, we1);
    } else {
        for (; e < E; ++e)
            l2_edge(g_ft2[src[e]], g_ft2[dst[e]], dst[e], ef[e],
                    al0, al1, ar0, ar1, ae0, ae1, we0, we1);
    }
}

__global__ void k_node2(const float* __restrict__ b2) {
    int n = blockIdx.x * blockDim.x + threadIdx.x;
    if (n >= NN) return;
    float4 a = *(const float4*)&g_A2[4 * n];
    g_xfin[n] = a.y / a.x + a.w / a.z + b2[0] + b2[1];
}

// pass 4: edge output (4 edges/thread, vector store)
__global__ void k_out(const int* __restrict__ src, const int* __restrict__ dst,
                      float* __restrict__ out, int E) {
    int t = blockIdx.x * blockDim.x + threadIdx.x;
    int e = 4 * t;
    if (e + 3 < E) {
        int4 s = *(const int4*)(src + e);
        int4 d = *(const int4*)(dst + e);
        float xsx = g_xfin[s.x], xsy = g_xfin[s.y], xsz = g_xfin[s.z], xsw = g_xfin[s.w];
        float xdx = g_xfin[d.x], xdy = g_xfin[d.y], xdz = g_xfin[d.z], xdw = g_xfin[d.w];
        *(float4*)(out + e) = make_float4(sqrtf(xsx * xdx), sqrtf(xsy * xdy),
                                          sqrtf(xsz * xdz), sqrtf(xsw * xdw));
    } else {
        for (; e < E; ++e) out[e] = sqrtf(g_xfin[src[e]] * g_xfin[dst[e]]);
    }
}

extern "C" void kernel_launch(void* const* d_in, const int* in_sizes, int n_in,
                              void* d_out, int out_size) {
    const int*   src = (const int*)d_in[0];
    const int*   dst = (const int*)d_in[1];
    const float* cap = (const float*)d_in[2];
    const float* ef  = (const float*)d_in[3];
    const float* W1  = (const float*)d_in[4];
    const float* We1 = (const float*)d_in[5];
    const float* al1 = (const float*)d_in[6];
    const float* ar1 = (const float*)d_in[7];
    const float* ae1 = (const float*)d_in[8];
    const float* b1  = (const float*)d_in[9];
    const float* W2  = (const float*)d_in[10];
    const float* We2 = (const float*)d_in[11];
    const float* al2 = (const float*)d_in[12];
    const float* ar2 = (const float*)d_in[13];
    const float* ae2 = (const float*)d_in[14];
    const float* b2  = (const float*)d_in[15];
    float* out = (float*)d_out;

    const int E = in_sizes[0];
    const int TB = 256;
    const int E4 = (E + 3) / 4;
    const int eb4 = (E4 + TB - 1) / TB;
    const int nb  = (NN + TB - 1) / TB;
    const int nb8 = (8 * NN + TB - 1) / TB;

    k_init<<<nb8, TB>>>(W1, We1, al1, ar1, ae1);
    k_sumcap<<<eb4, TB>>>(dst, cap, E);
    k_l1<<<eb4, TB>>>(src, dst, ef, E);
    k_node1<<<nb, TB>>>(W1, We1, b1, W2);
    k_l2<<<eb4, TB>>>(src, dst, ef, We2, al2, ar2, ae2, E);
    k_node2<<<nb, TB>>>(b2);
    k_out<<<eb4, TB>>>(src, dst, out, E);
}

// round 6
// speedup vs baseline: 2.4156x; 1.0182x over previous
#include <cuda_runtime.h>
#include <cuda_fp16.h>
#include <math.h>

#define NN 50000
#define SLOPE 0.2f
#define NSM 148
#define TBL 1024

// ---- scratch (alloc-free: __device__ globals) ----
__device__ float  g_sumcap[NN];
__device__ __align__(16) float g_A1[8 * NN];   // {e0, e0*ss, e0*f, e1, e1*ss, e1*f, pad, pad}
__device__ __align__(16) float g_A2[4 * NN];   // {e0, m0, e1, m1}
__device__ __align__(16) __half2 g_ft2h[NN];   // both layer-2 heads packed in 4B
__device__ float  g_xfin[NN];
__device__ float  g_c1[6];                     // cl1[2], cr1[2], ce1[2]

// init scratch (vectorized) + collapsed layer-1 attention coefficients
__global__ void k_init(const float* __restrict__ W1, const float* __restrict__ We1,
                       const float* __restrict__ al1, const float* __restrict__ ar1,
                       const float* __restrict__ ae1) {
    int i = blockIdx.x * blockDim.x + threadIdx.x;
    float4 z = make_float4(0.f, 0.f, 0.f, 0.f);
    if (i < 2 * NN)     ((float4*)g_A1)[i] = z;       // 8*NN floats = 2*NN float4
    if (i < NN)         ((float4*)g_A2)[i] = z;       // 4*NN floats = NN float4
    if (i < NN / 4)     ((float4*)g_sumcap)[i] = z;
    if (i < 2) {
        int h = i;
        float cl = 0.f, cr = 0.f, ce = 0.f;
        #pragma unroll
        for (int d = 0; d < 16; ++d) {
            float w = W1[h * 16 + d];
            cl += w * al1[h * 16 + d];
            cr += w * ar1[h * 16 + d];
            ce += We1[h * 16 + d] * ae1[h * 16 + d];
        }
        g_c1[h] = cl; g_c1[2 + h] = cr; g_c1[4 + h] = ce;
    }
}

// pass 1: per-node sum of incoming capacities (scatter red, 4 edges/thread)
__global__ void k_sumcap(const int* __restrict__ dst, const float* __restrict__ cap, int E) {
    int t = blockIdx.x * blockDim.x + threadIdx.x;
    int e = 4 * t;
    if (e + 3 < E) {
        int4   d = __ldcs((const int4*)(dst + e));
        float4 c = __ldcs((const float4*)(cap + e));
        atomicAdd(&g_sumcap[d.x], c.x);
        atomicAdd(&g_sumcap[d.y], c.y);
        atomicAdd(&g_sumcap[d.z], c.z);
        atomicAdd(&g_sumcap[d.w], c.w);
    } else {
        for (; e < E; ++e) atomicAdd(&g_sumcap[dst[e]], cap[e]);
    }
}

// pass 2: layer-1 fused softmax num/den accumulation.
// All node gathers come from an smem-resident copy of sumcap (200KB).
__device__ __forceinline__ void l1_accum(int d, float ss, float sd, float f,
                                         float c0, float c1, float c2,
                                         float c3, float c4, float c5) {
    float v0 = c0 * ss + c2 * sd + c4 * f;
    v0 = v0 > 0.f ? v0 : SLOPE * v0;
    float e0 = __expf(v0);
    float v1 = c1 * ss + c3 * sd + c5 * f;
    v1 = v1 > 0.f ? v1 : SLOPE * v1;
    float e1 = __expf(v1);
    atomicAdd((float4*)&g_A1[8 * d], make_float4(e0, e0 * ss, e0 * f, e1));
    atomicAdd((float2*)&g_A1[8 * d + 4], make_float2(e1 * ss, e1 * f));
}

__global__ void __launch_bounds__(TBL, 1)
k_l1(const int* __restrict__ src, const int* __restrict__ dst,
     const float* __restrict__ ef, int E) {
    extern __shared__ float s_cap[];
    {   // fill smem with the whole sumcap array (float4 copies)
        const float4* g4 = (const float4*)g_sumcap;
        float4* s4 = (float4*)s_cap;
        for (int i = threadIdx.x; i < NN / 4; i += TBL) s4[i] = g4[i];
    }
    __syncthreads();
    float c0 = g_c1[0], c1 = g_c1[1], c2 = g_c1[2],
          c3 = g_c1[3], c4 = g_c1[4], c5 = g_c1[5];
    int EQ = E >> 2;
    for (int q = blockIdx.x * TBL + threadIdx.x; q < EQ; q += gridDim.x * TBL) {
        int e = 4 * q;
        int4   s = __ldcs((const int4*)(src + e));
        int4   d = __ldcs((const int4*)(dst + e));
        float4 f = __ldcs((const float4*)(ef + e));
        float ssx = s_cap[s.x], ssy = s_cap[s.y], ssz = s_cap[s.z], ssw = s_cap[s.w];
        float sdx = s_cap[d.x], sdy = s_cap[d.y], sdz = s_cap[d.z], sdw = s_cap[d.w];
        l1_accum(d.x, ssx, sdx, f.x, c0, c1, c2, c3, c4, c5);
        l1_accum(d.y, ssy, sdy, f.y, c0, c1, c2, c3, c4, c5);
        l1_accum(d.z, ssz, sdz, f.z, c0, c1, c2, c3, c4, c5);
        l1_accum(d.w, ssw, sdw, f.w, c0, c1, c2, c3, c4, c5);
    }
    if (blockIdx.x == 0 && threadIdx.x == 0) {          // tail (E % 4)
        for (int e = EQ * 4; e < E; ++e)
            l1_accum(dst[e], s_cap[src[e]], s_cap[dst[e]], ef[e], c0, c1, c2, c3, c4, c5);
    }
}

// node: normalize, reconstruct x[n,16] = relu(.), project to layer-2 feats (fp16 pack)
__global__ void k_node1(const float* __restrict__ W1, const float* __restrict__ We1,
                        const float* __restrict__ b1, const float* __restrict__ W2) {
    int n = blockIdx.x * blockDim.x + threadIdx.x;
    if (n >= NN) return;
    float4 a = *(const float4*)&g_A1[8 * n];
    float2 b = *(const float2*)&g_A1[8 * n + 4];
    float inv0 = 1.f / a.x, inv1 = 1.f / a.w;   // self-loop guarantees > 0
    float s10 = a.y * inv0, s20 = a.z * inv0;
    float s11 = b.x * inv1, s21 = b.y * inv1;
    float ft0 = 0.f, ft1 = 0.f;
    #pragma unroll
    for (int d = 0; d < 16; ++d) {
        float x = W1[d] * s10 + We1[d] * s20 + b1[d]
                + W1[16 + d] * s11 + We1[16 + d] * s21 + b1[16 + d];
        x = fmaxf(x, 0.f);
        ft0 += x * W2[2 * d];
        ft1 += x * W2[2 * d + 1];
    }
    g_ft2h[n] = __floats2half2_rn(ft0, ft1);
}

// pass 3: layer-2 fused attention accumulation; ft2 gathers from smem (half2, 195KB)
__device__ __forceinline__ void l2_accum(float2 fts, float2 ftd, int d, float f,
                                         float al0, float al1, float ar0, float ar1,
                                         float ae0, float ae1, float we0, float we1) {
    float w0 = we0 * f, w1 = we1 * f;
    float v0 = al0 * fts.x + ar0 * ftd.x + ae0 * w0;
    v0 = v0 > 0.f ? v0 : SLOPE * v0;
    float e0 = __expf(v0);
    float v1 = al1 * fts.y + ar1 * ftd.y + ae1 * w1;
    v1 = v1 > 0.f ? v1 : SLOPE * v1;
    float e1 = __expf(v1);
    atomicAdd((float4*)&g_A2[4 * d],
              make_float4(e0, e0 * (fts.x + w0), e1, e1 * (fts.y + w1)));
}

__global__ void __launch_bounds__(TBL, 1)
k_l2(const int* __restrict__ src, const int* __restrict__ dst,
     const float* __restrict__ ef,
     const float* __restrict__ We2, const float* __restrict__ al2,
     const float* __restrict__ ar2, const float* __restrict__ ae2, int E) {
    extern __shared__ __half2 s_ft[];
    {   // fill smem with all ft2 (half2 = 4B/node; float4 copies)
        const float4* g4 = (const float4*)g_ft2h;
        float4* s4 = (float4*)s_ft;
        for (int i = threadIdx.x; i < NN / 4; i += TBL) s4[i] = g4[i];
    }
    __syncthreads();
    float al0 = al2[0], al1 = al2[1], ar0 = ar2[0], ar1 = ar2[1];
    float ae0 = ae2[0], ae1 = ae2[1], we0 = We2[0], we1 = We2[1];
    int EQ = E >> 2;
    for (int q = blockIdx.x * TBL + threadIdx.x; q < EQ; q += gridDim.x * TBL) {
        int e = 4 * q;
        int4   s = __ldcs((const int4*)(src + e));
        int4   d = __ldcs((const int4*)(dst + e));
        float4 f = __ldcs((const float4*)(ef + e));
        float2 fsx = __half22float2(s_ft[s.x]), fsy = __half22float2(s_ft[s.y]);
        float2 fsz = __half22float2(s_ft[s.z]), fsw = __half22float2(s_ft[s.w]);
        float2 fdx = __half22float2(s_ft[d.x]), fdy = __half22float2(s_ft[d.y]);
        float2 fdz = __half22float2(s_ft[d.z]), fdw = __half22float2(s_ft[d.w]);
        l2_accum(fsx, fdx, d.x, f.x, al0, al1, ar0, ar1, ae0, ae1, we0, we1);
        l2_accum(fsy, fdy, d.y, f.y, al0, al1, ar0, ar1, ae0, ae1, we0, we1);
        l2_accum(fsz, fdz, d.z, f.z, al0, al1, ar0, ar1, ae0, ae1, we0, we1);
        l2_accum(fsw, fdw, d.w, f.w, al0, al1, ar0, ar1, ae0, ae1, we0, we1);
    }
    if (blockIdx.x == 0 && threadIdx.x == 0) {
        for (int e = EQ * 4; e < E; ++e)
            l2_accum(__half22float2(s_ft[src[e]]), __half22float2(s_ft[dst[e]]),
                     dst[e], ef[e], al0, al1, ar0, ar1, ae0, ae1, we0, we1);
    }
}

__global__ void k_node2(const float* __restrict__ b2) {
    int n = blockIdx.x * blockDim.x + threadIdx.x;
    if (n >= NN) return;
    float4 a = *(const float4*)&g_A2[4 * n];
    g_xfin[n] = a.y / a.x + a.w / a.z + b2[0] + b2[1];
}

// pass 4: edge output; xfin gathers from smem (200KB), vector stores
__global__ void __launch_bounds__(TBL, 1)
k_out(const int* __restrict__ src, const int* __restrict__ dst,
      float* __restrict__ out, int E) {
    extern __shared__ float s_x[];
    {
        const float4* g4 = (const float4*)g_xfin;
        float4* s4 = (float4*)s_x;
        for (int i = threadIdx.x; i < NN / 4; i += TBL) s4[i] = g4[i];
    }
    __syncthreads();
    int EQ = E >> 2;
    for (int q = blockIdx.x * TBL + threadIdx.x; q < EQ; q += gridDim.x * TBL) {
        int e = 4 * q;
        int4 s = __ldcs((const int4*)(src + e));
        int4 d = __ldcs((const int4*)(dst + e));
        float4 r = make_float4(sqrtf(s_x[s.x] * s_x[d.x]), sqrtf(s_x[s.y] * s_x[d.y]),
                               sqrtf(s_x[s.z] * s_x[d.z]), sqrtf(s_x[s.w] * s_x[d.w]));
        *(float4*)(out + e) = r;
    }
    if (blockIdx.x == 0 && threadIdx.x == 0) {
        for (int e = EQ * 4; e < E; ++e)
            out[e] = sqrtf(s_x[src[e]] * s_x[dst[e]]);
    }
}

extern "C" void kernel_launch(void* const* d_in, const int* in_sizes, int n_in,
                              void* d_out, int out_size) {
    const int*   src = (const int*)d_in[0];
    const int*   dst = (const int*)d_in[1];
    const float* cap = (const float*)d_in[2];
    const float* ef  = (const float*)d_in[3];
    const float* W1  = (const float*)d_in[4];
    const float* We1 = (const float*)d_in[5];
    const float* al1 = (const float*)d_in[6];
    const float* ar1 = (const float*)d_in[7];
    const float* ae1 = (const float*)d_in[8];
    const float* b1  = (const float*)d_in[9];
    const float* W2  = (const float*)d_in[10];
    const float* We2 = (const float*)d_in[11];
    const float* al2 = (const float*)d_in[12];
    const float* ar2 = (const float*)d_in[13];
    const float* ae2 = (const float*)d_in[14];
    const float* b2  = (const float*)d_in[15];
    float* out = (float*)d_out;

    const int E = in_sizes[0];
    const int SMEM = NN * 4;   // 200000 bytes
    cudaFuncSetAttribute(k_l1,  cudaFuncAttributeMaxDynamicSharedMemorySize, SMEM);
    cudaFuncSetAttribute(k_l2,  cudaFuncAttributeMaxDynamicSharedMemorySize, SMEM);
    cudaFuncSetAttribute(k_out, cudaFuncAttributeMaxDynamicSharedMemorySize, SMEM);

    const int TB = 256;
    const int E4  = (E + 3) / 4;
    const int eb4 = (E4 + TB - 1) / TB;
    const int nb  = (NN + TB - 1) / TB;
    const int zb  = (2 * NN + TB - 1) / TB;   // covers largest zero range (float4 count)

    k_init<<<zb, TB>>>(W1, We1, al1, ar1, ae1);
    k_sumcap<<<eb4, TB>>>(dst, cap, E);
    k_l1<<<NSM, TBL, SMEM>>>(src, dst, ef, E);
    k_node1<<<nb, TB>>>(W1, We1, b1, W2);
    k_l2<<<NSM, TBL, SMEM>>>(src, dst, ef, We2, al2, ar2, ae2, E);
    k_node2<<<nb, TB>>>(b2);
    k_out<<<NSM, TBL, SMEM>>>(src, dst, out, E);
}